// round 16
// baseline (speedup 1.0000x reference)
#include <cuda_runtime.h>
#include <cuda_fp16.h>

// InstHead fused. R16: pass2 = exact R14 revert (register epilogue vectors,
// 4 CTAs/SM). pass1: Wf -> SMEM fragment layout (like smf), 5 CTAs/SM.

#define C 32
#define WPB 4
typedef unsigned int u32;

__device__ __forceinline__ u32 packh2(float x, float y) {
    __half2 h = __floats2half2_rn(x, y);
    return *(u32*)&h;
}
__device__ __forceinline__ void split_h2(float x, float y, u32& hi, u32& lo) {
    __half2 h = __floats2half2_rn(x, y);
    float2 b = __half22float2(h);
    __half2 l = __floats2half2_rn(x - b.x, y - b.y);
    hi = *(u32*)&h;
    lo = *(u32*)&l;
}

#define MMA16(d0,d1,d2,d3,a0,a1,a2,a3,b0,b1) \
    asm("mma.sync.aligned.m16n8k16.row.col.f32.f16.f16.f32 " \
        "{%0,%1,%2,%3}, {%4,%5,%6,%7}, {%8,%9}, {%0,%1,%2,%3};" \
        : "+f"(d0), "+f"(d1), "+f"(d2), "+f"(d3) \
        : "r"(a0), "r"(a1), "r"(a2), "r"(a3), "r"(b0), "r"(b1))

// ---- scratch ----
__device__ float g_pool[64 * C];
__device__ float g_cnt[64];
__device__ float g_sumH[C];
__device__ float g_sumH2[C];
__device__ float g_w1f[C * C];
__device__ float g_b1f[C];

__global__ void zero_kernel(int B) {
    int t = threadIdx.x;
    for (int i = t; i < B * C; i += blockDim.x) g_pool[i] = 0.f;
    if (t < B) g_cnt[t] = 0.f;
    if (t < C) { g_sumH[t] = 0.f; g_sumH2[t] = 0.f; }
}

#define XP 36
#define TP 32
#define CH(i, tg) (((i) >> 1) * 8 + 2 * (tg) + ((i) & 1))

__device__ __forceinline__ void load_afrag_hi_acc(
    const float* SX, int m, int kc, int grp, int tg, u32* ah,
    float2& q0, float2& q1)
{
    int r = m * 16 + grp;
    const float* p0 = &SX[r * XP + kc * 16 + 2 * tg];
    const float* p1 = &SX[(r + 8) * XP + kc * 16 + 2 * tg];
    float2 v0 = *(const float2*)p0;
    float2 v1 = *(const float2*)p1;
    float2 v2 = *(const float2*)(p0 + 8);
    float2 v3 = *(const float2*)(p1 + 8);
    ah[0] = packh2(v0.x, v0.y);
    ah[1] = packh2(v1.x, v1.y);
    ah[2] = packh2(v2.x, v2.y);
    ah[3] = packh2(v3.x, v3.y);
    q0.x += v0.x + v1.x;  q0.y += v0.y + v1.y;
    q1.x += v2.x + v3.x;  q1.y += v2.y + v3.y;
}

// ================= PASS 1 =================
__global__ void __launch_bounds__(32 * WPB, 5) pass1_kernel(
    const float* __restrict__ feats, const int* __restrict__ bidx,
    const float* __restrict__ w1,
    const float* __restrict__ mw1, const float* __restrict__ mb1,
    const float* __restrict__ mw2, const float* __restrict__ mb2,
    float* __restrict__ mask_out, int n, int tiles_total, int tpw)
{
    __shared__ float sx[WPB][TP * XP];
    __shared__ u32   smf[512];   // mask weights
    __shared__ u32   swf[512];   // h weights
    __shared__ float s_mb1[C];
    __shared__ float s_mw2[C];

    const int lane = threadIdx.x & 31;
    const int wi   = threadIdx.x >> 5;
    const int tg   = lane & 3;
    const int grp  = lane >> 2;

    for (int e = threadIdx.x; e < 512; e += 32 * WPB) {
        int kc = e >> 8, nb = (e >> 6) & 3, j = (e >> 5) & 1, ln = e & 31;
        int col = nb * 8 + (ln >> 2);
        int k0  = kc * 16 + 2 * (ln & 3) + 8 * j;
        smf[e] = packh2(mw1[k0 * C + col], mw1[(k0 + 1) * C + col]);
        swf[e] = packh2(w1[k0 * C + col],  w1[(k0 + 1) * C + col]);
    }
    if (threadIdx.x < C) {
        s_mb1[threadIdx.x] = mb1[threadIdx.x];
        s_mw2[threadIdx.x] = mw2[threadIdx.x];
    }
    __syncthreads();

    const float mb2v = mb2[0];

    float s[8], s2[8];
#pragma unroll
    for (int i = 0; i < 8; i++) { s[i] = 0.f; s2[i] = 0.f; }

    float2 pq[2][2];
#pragma unroll
    for (int a = 0; a < 2; a++)
#pragma unroll
        for (int bq = 0; bq < 2; bq++) pq[a][bq] = make_float2(0.f, 0.f);
    int pcnt = 0, cur_b = -1;

    const int gwid = blockIdx.x * WPB + wi;
    int t0 = gwid * tpw;
    int t1 = t0 + tpw; if (t1 > tiles_total) t1 = tiles_total;
    if (t0 >= t1) return;

    float* SX = sx[wi];

    auto flush = [&]() {
        if (cur_b < 0) return;
        float vals[8] = { pq[0][0].x, pq[0][0].y, pq[0][1].x, pq[0][1].y,
                          pq[1][0].x, pq[1][0].y, pq[1][1].x, pq[1][1].y };
#pragma unroll
        for (int i = 0; i < 8; i++) {
#pragma unroll
            for (int o = 4; o < 32; o <<= 1)
                vals[i] += __shfl_xor_sync(0xffffffffu, vals[i], o);
        }
        if (grp == 0) {
#pragma unroll
            for (int i = 0; i < 8; i++) {
                int ch = (i >> 2) * 16 + ((i >> 1) & 1) * 8 + 2 * tg + (i & 1);
                atomicAdd(&g_pool[cur_b * C + ch], vals[i]);
            }
        }
        if (lane == 0) atomicAdd(&g_cnt[cur_b], (float)pcnt);
#pragma unroll
        for (int a = 0; a < 2; a++)
#pragma unroll
            for (int bq = 0; bq < 2; bq++) pq[a][bq] = make_float2(0.f, 0.f);
        pcnt = 0;
    };

    int v0 = n - t0 * TP; if (v0 > TP) v0 = TP;
    int bf = bidx[t0 * TP];
    int bl = bidx[t0 * TP + v0 - 1];

    for (int tile = t0; tile < t1; tile++) {
        const int base = tile * TP;
        int valid = n - base; if (valid > TP) valid = TP;
        const int lim = valid * 8;
        const bool has_next = (tile + 1 < t1);

        int nbf = 0, nbl = 0;
        if (has_next) {
            int nb2 = (tile + 1) * TP;
            int nv = n - nb2; if (nv > TP) nv = TP;
            nbf = __ldg(&bidx[nb2]);
            nbl = __ldg(&bidx[nb2 + nv - 1]);
        }

        const float4* src = (const float4*)(feats + (size_t)base * C);
#pragma unroll
        for (int j = 0; j < 8; j++) {
            int L = lane + 32 * j;
            float4 v = make_float4(0.f, 0.f, 0.f, 0.f);
            if (L < lim) v = src[L];
            *(float4*)&SX[(L >> 3) * XP + 4 * (L & 7)] = v;
        }
        __syncwarp();

        const bool uniform = (bf == bl);

        u32 ah[2][2][4];
        if (uniform) {
            if (bf != cur_b) { flush(); cur_b = bf; }
#pragma unroll
            for (int m = 0; m < 2; m++)
#pragma unroll
                for (int kc = 0; kc < 2; kc++)
                    load_afrag_hi_acc(SX, m, kc, grp, tg, ah[m][kc],
                                      pq[kc][0], pq[kc][1]);
            pcnt += valid;
        } else {
            flush(); cur_b = -1;
            float2 dump0 = make_float2(0.f, 0.f), dump1 = dump0;
#pragma unroll
            for (int m = 0; m < 2; m++)
#pragma unroll
                for (int kc = 0; kc < 2; kc++)
                    load_afrag_hi_acc(SX, m, kc, grp, tg, ah[m][kc],
                                      dump0, dump1);
            for (int pnt = 0; pnt < valid; pnt++) {
                int b = bidx[base + pnt];
                atomicAdd(&g_pool[b * C + lane], SX[pnt * XP + lane]);
                if (lane == 0) atomicAdd(&g_cnt[b], 1.f);
            }
        }
        bf = nbf; bl = nbl;

        const bool full = (valid == TP);

        // --- h GEMM (1-term, bias-free, weights from SMEM) + stats ---
#pragma unroll
        for (int nb = 0; nb < 4; nb++) {
            float d[2][4];
#pragma unroll
            for (int m = 0; m < 2; m++) {
                d[m][0] = 0.f; d[m][1] = 0.f; d[m][2] = 0.f; d[m][3] = 0.f;
            }
#pragma unroll
            for (int kc = 0; kc < 2; kc++) {
                u32 b0 = swf[(kc * 4 + nb) * 64 + lane];
                u32 b1 = swf[(kc * 4 + nb) * 64 + 32 + lane];
#pragma unroll
                for (int m = 0; m < 2; m++) {
                    MMA16(d[m][0], d[m][1], d[m][2], d[m][3],
                          ah[m][kc][0], ah[m][kc][1], ah[m][kc][2], ah[m][kc][3],
                          b0, b1);
                }
            }
            if (full) {
#pragma unroll
                for (int m = 0; m < 2; m++) {
                    s[2 * nb]      += d[m][0] + d[m][2];
                    s2[2 * nb]      = fmaf(d[m][0], d[m][0], fmaf(d[m][2], d[m][2], s2[2 * nb]));
                    s[2 * nb + 1]  += d[m][1] + d[m][3];
                    s2[2 * nb + 1]  = fmaf(d[m][1], d[m][1], fmaf(d[m][3], d[m][3], s2[2 * nb + 1]));
                }
            } else {
#pragma unroll
                for (int m = 0; m < 2; m++) {
                    if (base + m * 16 + grp < n) {
                        s[2 * nb] += d[m][0];     s2[2 * nb]     = fmaf(d[m][0], d[m][0], s2[2 * nb]);
                        s[2 * nb + 1] += d[m][1]; s2[2 * nb + 1] = fmaf(d[m][1], d[m][1], s2[2 * nb + 1]);
                    }
                    if (base + m * 16 + grp + 8 < n) {
                        s[2 * nb] += d[m][2];     s2[2 * nb]     = fmaf(d[m][2], d[m][2], s2[2 * nb]);
                        s[2 * nb + 1] += d[m][3]; s2[2 * nb + 1] = fmaf(d[m][3], d[m][3], s2[2 * nb + 1]);
                    }
                }
            }
        }

        // --- mask GEMM (1-term, weights from SMEM) + projection ---
        float p[2][2] = {{0.f, 0.f}, {0.f, 0.f}};
#pragma unroll
        for (int nb = 0; nb < 4; nb++) {
            float mb0 = s_mb1[nb * 8 + 2 * tg];
            float mb1v = s_mb1[nb * 8 + 2 * tg + 1];
            float d[2][4];
#pragma unroll
            for (int m = 0; m < 2; m++) {
                d[m][0] = mb0; d[m][1] = mb1v; d[m][2] = mb0; d[m][3] = mb1v;
            }
#pragma unroll
            for (int kc = 0; kc < 2; kc++) {
                u32 b0 = smf[(kc * 4 + nb) * 64 + lane];
                u32 b1 = smf[(kc * 4 + nb) * 64 + 32 + lane];
#pragma unroll
                for (int m = 0; m < 2; m++) {
                    MMA16(d[m][0], d[m][1], d[m][2], d[m][3],
                          ah[m][kc][0], ah[m][kc][1], ah[m][kc][2], ah[m][kc][3],
                          b0, b1);
                }
            }
            float mw0 = s_mw2[nb * 8 + 2 * tg];
            float mw1v = s_mw2[nb * 8 + 2 * tg + 1];
#pragma unroll
            for (int m = 0; m < 2; m++) {
                p[m][0] = fmaf(fmaxf(d[m][0], 0.f), mw0,
                          fmaf(fmaxf(d[m][1], 0.f), mw1v, p[m][0]));
                p[m][1] = fmaf(fmaxf(d[m][2], 0.f), mw0,
                          fmaf(fmaxf(d[m][3], 0.f), mw1v, p[m][1]));
            }
        }
#pragma unroll
        for (int m = 0; m < 2; m++) {
            p[m][0] += __shfl_xor_sync(0xffffffffu, p[m][0], 1);
            p[m][0] += __shfl_xor_sync(0xffffffffu, p[m][0], 2);
            p[m][1] += __shfl_xor_sync(0xffffffffu, p[m][1], 1);
            p[m][1] += __shfl_xor_sync(0xffffffffu, p[m][1], 2);
        }
        if (tg == 0) {
#pragma unroll
            for (int m = 0; m < 2; m++) {
                int r = m * 16 + grp;
                if (r < valid)     mask_out[base + r]     = p[m][0] + mb2v;
                if (r + 8 < valid) mask_out[base + r + 8] = p[m][1] + mb2v;
            }
        }
        __syncwarp();
    }

    flush();
#pragma unroll
    for (int i = 0; i < 8; i++) {
#pragma unroll
        for (int o = 4; o < 32; o <<= 1) {
            s[i]  += __shfl_xor_sync(0xffffffffu, s[i],  o);
            s2[i] += __shfl_xor_sync(0xffffffffu, s2[i], o);
        }
    }
    if (grp == 0) {
#pragma unroll
        for (int i = 0; i < 8; i++) {
            int ch = CH(i, tg);
            atomicAdd(&g_sumH[ch],  s[i]);
            atomicAdd(&g_sumH2[ch], s2[i]);
        }
    }
}

// ================= FINALIZE =================
__global__ void finalize_kernel(
    const float* __restrict__ w1,
    const float* __restrict__ gamma, const float* __restrict__ beta,
    const float* __restrict__ iou_w, const float* __restrict__ iou_b,
    float* __restrict__ out_pooled, float* __restrict__ out_iou,
    int n, int B)
{
    int t = threadIdx.x;
    float inv = 1.f / (float)n;
    float mu  = g_sumH[t] * inv;
    float var = g_sumH2[t] * inv - mu * mu;
    float sc  = gamma[t] * rsqrtf(var + 1e-4f);
    g_b1f[t] = beta[t] - mu * sc;
#pragma unroll
    for (int k = 0; k < C; k++) g_w1f[k * C + t] = w1[k * C + t] * sc;

    float iw = iou_w[t];
    for (int b = 0; b < B; b++) {
        float cnt = fmaxf(g_cnt[b], 1.f);
        float pm  = g_pool[b * C + t] / cnt;
        out_pooled[b * C + t] = pm;
        float v = pm * iw;
#pragma unroll
        for (int o = 16; o > 0; o >>= 1) v += __shfl_xor_sync(0xffffffffu, v, o);
        if (t == 0) out_iou[b] = v + iou_b[0];
    }
}

// ================= PASS 2 (exact R14 form) =================
__global__ void __launch_bounds__(32 * WPB, 4) pass2_kernel(
    const float* __restrict__ feats,
    const float* __restrict__ w2, const float* __restrict__ ob2,
    float* __restrict__ off_out, int n, int tiles_total, int tpw)
{
    __shared__ float sx[WPB][TP * XP];

    const int lane = threadIdx.x & 31;
    const int wi   = threadIdx.x >> 5;
    const int tg   = lane & 3;
    const int grp  = lane >> 2;

    u32 Wf[2][4][2];
#pragma unroll
    for (int kc = 0; kc < 2; kc++)
#pragma unroll
        for (int nb = 0; nb < 4; nb++) {
            int col = nb * 8 + grp;
            int k0 = kc * 16 + 2 * tg;
            Wf[kc][nb][0] = packh2(g_w1f[k0 * C + col],       g_w1f[(k0 + 1) * C + col]);
            Wf[kc][nb][1] = packh2(g_w1f[(k0 + 8) * C + col], g_w1f[(k0 + 9) * C + col]);
        }
    float fb[8], w2v0[8], w2v1[8], w2v2[8];
#pragma unroll
    for (int i = 0; i < 8; i++) {
        int ch = CH(i, tg);
        fb[i]   = g_b1f[ch];
        w2v0[i] = w2[ch * 3 + 0];
        w2v1[i] = w2[ch * 3 + 1];
        w2v2[i] = w2[ch * 3 + 2];
    }
    const float c0 = ob2[0], c1 = ob2[1], c2 = ob2[2];

    const int gwid = blockIdx.x * WPB + wi;
    int t0 = gwid * tpw;
    int t1 = t0 + tpw; if (t1 > tiles_total) t1 = tiles_total;

    float* SX = sx[wi];

    for (int tile = t0; tile < t1; tile++) {
        const int base = tile * TP;
        int valid = n - base; if (valid > TP) valid = TP;
        const int lim = valid * 8;
        const float4* src = (const float4*)(feats + (size_t)base * C);
#pragma unroll
        for (int j = 0; j < 8; j++) {
            int L = lane + 32 * j;
            float4 v = make_float4(0.f, 0.f, 0.f, 0.f);
            if (L < lim) v = src[L];
            *(float4*)&SX[(L >> 3) * XP + 4 * (L & 7)] = v;
        }
        __syncwarp();

        u32 ah[2][2][4], al[2][2][4];
#pragma unroll
        for (int m = 0; m < 2; m++)
#pragma unroll
            for (int kc = 0; kc < 2; kc++) {
                int r = m * 16 + grp;
                const float* p0 = &SX[r * XP + kc * 16 + 2 * tg];
                const float* p1 = &SX[(r + 8) * XP + kc * 16 + 2 * tg];
                float2 v0 = *(const float2*)p0;
                float2 v1 = *(const float2*)p1;
                float2 v2 = *(const float2*)(p0 + 8);
                float2 v3 = *(const float2*)(p1 + 8);
                split_h2(v0.x, v0.y, ah[m][kc][0], al[m][kc][0]);
                split_h2(v1.x, v1.y, ah[m][kc][1], al[m][kc][1]);
                split_h2(v2.x, v2.y, ah[m][kc][2], al[m][kc][2]);
                split_h2(v3.x, v3.y, ah[m][kc][3], al[m][kc][3]);
            }

        float o0[2][2], o1[2][2], o2[2][2];
#pragma unroll
        for (int m = 0; m < 2; m++)
#pragma unroll
            for (int r = 0; r < 2; r++) { o0[m][r] = 0.f; o1[m][r] = 0.f; o2[m][r] = 0.f; }

#pragma unroll
        for (int nb = 0; nb < 4; nb++) {
            float d[2][4];
#pragma unroll
            for (int m = 0; m < 2; m++) {
                d[m][0] = fb[2 * nb]; d[m][1] = fb[2 * nb + 1];
                d[m][2] = fb[2 * nb]; d[m][3] = fb[2 * nb + 1];
            }
#pragma unroll
            for (int kc = 0; kc < 2; kc++)
#pragma unroll
                for (int m = 0; m < 2; m++) {
                    MMA16(d[m][0], d[m][1], d[m][2], d[m][3],
                          al[m][kc][0], al[m][kc][1], al[m][kc][2], al[m][kc][3],
                          Wf[kc][nb][0], Wf[kc][nb][1]);
                    MMA16(d[m][0], d[m][1], d[m][2], d[m][3],
                          ah[m][kc][0], ah[m][kc][1], ah[m][kc][2], ah[m][kc][3],
                          Wf[kc][nb][0], Wf[kc][nb][1]);
                }
#pragma unroll
            for (int m = 0; m < 2; m++) {
                float e0 = fmaxf(d[m][0], 0.f), e1 = fmaxf(d[m][1], 0.f);
                float e2 = fmaxf(d[m][2], 0.f), e3 = fmaxf(d[m][3], 0.f);
                o0[m][0] = fmaf(e0, w2v0[2 * nb], fmaf(e1, w2v0[2 * nb + 1], o0[m][0]));
                o1[m][0] = fmaf(e0, w2v1[2 * nb], fmaf(e1, w2v1[2 * nb + 1], o1[m][0]));
                o2[m][0] = fmaf(e0, w2v2[2 * nb], fmaf(e1, w2v2[2 * nb + 1], o2[m][0]));
                o0[m][1] = fmaf(e2, w2v0[2 * nb], fmaf(e3, w2v0[2 * nb + 1], o0[m][1]));
                o1[m][1] = fmaf(e2, w2v1[2 * nb], fmaf(e3, w2v1[2 * nb + 1], o1[m][1]));
                o2[m][1] = fmaf(e2, w2v2[2 * nb], fmaf(e3, w2v2[2 * nb + 1], o2[m][1]));
            }
        }
#pragma unroll
        for (int m = 0; m < 2; m++)
#pragma unroll
            for (int r = 0; r < 2; r++) {
#pragma unroll
                for (int o = 1; o <= 2; o <<= 1) {
                    o0[m][r] += __shfl_xor_sync(0xffffffffu, o0[m][r], o);
                    o1[m][r] += __shfl_xor_sync(0xffffffffu, o1[m][r], o);
                    o2[m][r] += __shfl_xor_sync(0xffffffffu, o2[m][r], o);
                }
            }
        if (tg == 0) {
#pragma unroll
            for (int m = 0; m < 2; m++) {
#pragma unroll
                for (int r = 0; r < 2; r++) {
                    int row = m * 16 + grp + r * 8;
                    if (row < valid) {
                        size_t o = (size_t)(base + row) * 3;
                        off_out[o + 0] = o0[m][r] + c0;
                        off_out[o + 1] = o1[m][r] + c1;
                        off_out[o + 2] = o2[m][r] + c2;
                    }
                }
            }
        }
        __syncwarp();
    }
}

// ================= LAUNCH =================
extern "C" void kernel_launch(void* const* d_in, const int* in_sizes, int n_in,
                              void* d_out, int out_size) {
    const float* feats = (const float*)d_in[0];
    const int*   bidx  = (const int*)  d_in[1];
    const float* w1    = (const float*)d_in[2];
    const float* gamma = (const float*)d_in[4];
    const float* beta  = (const float*)d_in[5];
    const float* w2    = (const float*)d_in[6];
    const float* ob2   = (const float*)d_in[7];
    const float* mw1   = (const float*)d_in[8];
    const float* mb1   = (const float*)d_in[9];
    const float* mw2   = (const float*)d_in[10];
    const float* mb2   = (const float*)d_in[11];
    const float* iw    = (const float*)d_in[12];
    const float* ib    = (const float*)d_in[13];

    int n = in_sizes[1];
    int B = (out_size - 4 * n) / 33;
    if (B < 1) B = 1;
    if (B > 64) B = 64;

    float* out        = (float*)d_out;
    float* out_off    = out;
    float* out_mask   = out + (size_t)3 * n;
    float* out_pooled = out + (size_t)4 * n;
    float* out_iou    = out_pooled + (size_t)B * C;

    int tiles  = (n + TP - 1) / TP;
    int blocks = 608;
    int warps  = blocks * WPB;
    int tpw    = (tiles + warps - 1) / warps;

    zero_kernel<<<1, 1024>>>(B);
    pass1_kernel<<<blocks, 32 * WPB>>>(feats, bidx, w1, mw1, mb1, mw2, mb2,
                                       out_mask, n, tiles, tpw);
    finalize_kernel<<<1, 32>>>(w1, gamma, beta, iw, ib,
                               out_pooled, out_iou, n, B);
    pass2_kernel<<<blocks, 32 * WPB>>>(feats, w2, ob2, out_off, n, tiles, tpw);
}

// round 17
// speedup vs baseline: 1.1612x; 1.1612x over previous
#include <cuda_runtime.h>
#include <cuda_fp16.h>

// InstHead fused. R17: R14 base. (1) zero_kernel removed — finalize restores
// zeroed scratch invariant after reading. (2) pass2 cp.async SMEM double
// buffer (no register cost). pass1 = R14 exactly.

#define C 32
#define WPB 4
typedef unsigned int u32;

__device__ __forceinline__ u32 packh2(float x, float y) {
    __half2 h = __floats2half2_rn(x, y);
    return *(u32*)&h;
}
__device__ __forceinline__ void split_h2(float x, float y, u32& hi, u32& lo) {
    __half2 h = __floats2half2_rn(x, y);
    float2 b = __half22float2(h);
    __half2 l = __floats2half2_rn(x - b.x, y - b.y);
    hi = *(u32*)&h;
    lo = *(u32*)&l;
}

#define MMA16(d0,d1,d2,d3,a0,a1,a2,a3,b0,b1) \
    asm("mma.sync.aligned.m16n8k16.row.col.f32.f16.f16.f32 " \
        "{%0,%1,%2,%3}, {%4,%5,%6,%7}, {%8,%9}, {%0,%1,%2,%3};" \
        : "+f"(d0), "+f"(d1), "+f"(d2), "+f"(d3) \
        : "r"(a0), "r"(a1), "r"(a2), "r"(a3), "r"(b0), "r"(b1))

#define CP_ASYNC16(dst, src, nbytes) \
    asm volatile("cp.async.cg.shared.global [%0], [%1], 16, %2;" \
                 :: "r"(dst), "l"(src), "r"(nbytes))
#define CP_COMMIT() asm volatile("cp.async.commit_group;")
#define CP_WAIT1()  asm volatile("cp.async.wait_group 1;")
#define CP_WAIT0()  asm volatile("cp.async.wait_group 0;")

// ---- scratch (statically zero-initialized; finalize restores zeros) ----
__device__ float g_pool[64 * C];
__device__ float g_cnt[64];
__device__ float g_sumH[C];
__device__ float g_sumH2[C];
__device__ float g_w1f[C * C];
__device__ float g_b1f[C];

#define XP 36
#define TP 32
#define CH(i, tg) (((i) >> 1) * 8 + 2 * (tg) + ((i) & 1))

__device__ __forceinline__ void load_afrag_hi_acc(
    const float* SX, int m, int kc, int grp, int tg, u32* ah,
    float2& q0, float2& q1)
{
    int r = m * 16 + grp;
    const float* p0 = &SX[r * XP + kc * 16 + 2 * tg];
    const float* p1 = &SX[(r + 8) * XP + kc * 16 + 2 * tg];
    float2 v0 = *(const float2*)p0;
    float2 v1 = *(const float2*)p1;
    float2 v2 = *(const float2*)(p0 + 8);
    float2 v3 = *(const float2*)(p1 + 8);
    ah[0] = packh2(v0.x, v0.y);
    ah[1] = packh2(v1.x, v1.y);
    ah[2] = packh2(v2.x, v2.y);
    ah[3] = packh2(v3.x, v3.y);
    q0.x += v0.x + v1.x;  q0.y += v0.y + v1.y;
    q1.x += v2.x + v3.x;  q1.y += v2.y + v3.y;
}

// ================= PASS 1 (R14 exact) =================
__global__ void __launch_bounds__(32 * WPB, 4) pass1_kernel(
    const float* __restrict__ feats, const int* __restrict__ bidx,
    const float* __restrict__ w1,
    const float* __restrict__ mw1, const float* __restrict__ mb1,
    const float* __restrict__ mw2, const float* __restrict__ mb2,
    float* __restrict__ mask_out, int n, int tiles_total, int tpw)
{
    __shared__ float sx[WPB][TP * XP];
    __shared__ u32   smf[512];
    __shared__ float s_mb1[C];
    __shared__ float s_mw2[C];

    const int lane = threadIdx.x & 31;
    const int wi   = threadIdx.x >> 5;
    const int tg   = lane & 3;
    const int grp  = lane >> 2;

    for (int e = threadIdx.x; e < 512; e += 32 * WPB) {
        int kc = e >> 8, nb = (e >> 6) & 3, j = (e >> 5) & 1, ln = e & 31;
        int col = nb * 8 + (ln >> 2);
        int k0  = kc * 16 + 2 * (ln & 3) + 8 * j;
        smf[e] = packh2(mw1[k0 * C + col], mw1[(k0 + 1) * C + col]);
    }
    if (threadIdx.x < C) {
        s_mb1[threadIdx.x] = mb1[threadIdx.x];
        s_mw2[threadIdx.x] = mw2[threadIdx.x];
    }
    __syncthreads();

    u32 Wf[2][4][2];
#pragma unroll
    for (int kc = 0; kc < 2; kc++)
#pragma unroll
        for (int nb = 0; nb < 4; nb++) {
            int col = nb * 8 + grp;
            int k0 = kc * 16 + 2 * tg;
            Wf[kc][nb][0] = packh2(w1[k0 * C + col],       w1[(k0 + 1) * C + col]);
            Wf[kc][nb][1] = packh2(w1[(k0 + 8) * C + col], w1[(k0 + 9) * C + col]);
        }
    const float mb2v = mb2[0];

    float s[8], s2[8];
#pragma unroll
    for (int i = 0; i < 8; i++) { s[i] = 0.f; s2[i] = 0.f; }

    float2 pq[2][2];
#pragma unroll
    for (int a = 0; a < 2; a++)
#pragma unroll
        for (int bq = 0; bq < 2; bq++) pq[a][bq] = make_float2(0.f, 0.f);
    int pcnt = 0, cur_b = -1;

    const int gwid = blockIdx.x * WPB + wi;
    int t0 = gwid * tpw;
    int t1 = t0 + tpw; if (t1 > tiles_total) t1 = tiles_total;
    if (t0 >= t1) return;

    float* SX = sx[wi];

    auto flush = [&]() {
        if (cur_b < 0) return;
        float vals[8] = { pq[0][0].x, pq[0][0].y, pq[0][1].x, pq[0][1].y,
                          pq[1][0].x, pq[1][0].y, pq[1][1].x, pq[1][1].y };
#pragma unroll
        for (int i = 0; i < 8; i++) {
#pragma unroll
            for (int o = 4; o < 32; o <<= 1)
                vals[i] += __shfl_xor_sync(0xffffffffu, vals[i], o);
        }
        if (grp == 0) {
#pragma unroll
            for (int i = 0; i < 8; i++) {
                int ch = (i >> 2) * 16 + ((i >> 1) & 1) * 8 + 2 * tg + (i & 1);
                atomicAdd(&g_pool[cur_b * C + ch], vals[i]);
            }
        }
        if (lane == 0) atomicAdd(&g_cnt[cur_b], (float)pcnt);
#pragma unroll
        for (int a = 0; a < 2; a++)
#pragma unroll
            for (int bq = 0; bq < 2; bq++) pq[a][bq] = make_float2(0.f, 0.f);
        pcnt = 0;
    };

    int v0 = n - t0 * TP; if (v0 > TP) v0 = TP;
    int bf = bidx[t0 * TP];
    int bl = bidx[t0 * TP + v0 - 1];

    for (int tile = t0; tile < t1; tile++) {
        const int base = tile * TP;
        int valid = n - base; if (valid > TP) valid = TP;
        const int lim = valid * 8;
        const bool has_next = (tile + 1 < t1);

        int nbf = 0, nbl = 0;
        if (has_next) {
            int nb2 = (tile + 1) * TP;
            int nv = n - nb2; if (nv > TP) nv = TP;
            nbf = __ldg(&bidx[nb2]);
            nbl = __ldg(&bidx[nb2 + nv - 1]);
        }

        const float4* src = (const float4*)(feats + (size_t)base * C);
#pragma unroll
        for (int j = 0; j < 8; j++) {
            int L = lane + 32 * j;
            float4 v = make_float4(0.f, 0.f, 0.f, 0.f);
            if (L < lim) v = src[L];
            *(float4*)&SX[(L >> 3) * XP + 4 * (L & 7)] = v;
        }
        __syncwarp();

        const bool uniform = (bf == bl);

        u32 ah[2][2][4];
        if (uniform) {
            if (bf != cur_b) { flush(); cur_b = bf; }
#pragma unroll
            for (int m = 0; m < 2; m++)
#pragma unroll
                for (int kc = 0; kc < 2; kc++)
                    load_afrag_hi_acc(SX, m, kc, grp, tg, ah[m][kc],
                                      pq[kc][0], pq[kc][1]);
            pcnt += valid;
        } else {
            flush(); cur_b = -1;
            float2 dump0 = make_float2(0.f, 0.f), dump1 = dump0;
#pragma unroll
            for (int m = 0; m < 2; m++)
#pragma unroll
                for (int kc = 0; kc < 2; kc++)
                    load_afrag_hi_acc(SX, m, kc, grp, tg, ah[m][kc],
                                      dump0, dump1);
            for (int pnt = 0; pnt < valid; pnt++) {
                int b = bidx[base + pnt];
                atomicAdd(&g_pool[b * C + lane], SX[pnt * XP + lane]);
                if (lane == 0) atomicAdd(&g_cnt[b], 1.f);
            }
        }
        bf = nbf; bl = nbl;

        const bool full = (valid == TP);

#pragma unroll
        for (int nb = 0; nb < 4; nb++) {
            float d[2][4];
#pragma unroll
            for (int m = 0; m < 2; m++) {
                d[m][0] = 0.f; d[m][1] = 0.f; d[m][2] = 0.f; d[m][3] = 0.f;
            }
#pragma unroll
            for (int kc = 0; kc < 2; kc++)
#pragma unroll
                for (int m = 0; m < 2; m++) {
                    MMA16(d[m][0], d[m][1], d[m][2], d[m][3],
                          ah[m][kc][0], ah[m][kc][1], ah[m][kc][2], ah[m][kc][3],
                          Wf[kc][nb][0], Wf[kc][nb][1]);
                }
            if (full) {
#pragma unroll
                for (int m = 0; m < 2; m++) {
                    s[2 * nb]      += d[m][0] + d[m][2];
                    s2[2 * nb]      = fmaf(d[m][0], d[m][0], fmaf(d[m][2], d[m][2], s2[2 * nb]));
                    s[2 * nb + 1]  += d[m][1] + d[m][3];
                    s2[2 * nb + 1]  = fmaf(d[m][1], d[m][1], fmaf(d[m][3], d[m][3], s2[2 * nb + 1]));
                }
            } else {
#pragma unroll
                for (int m = 0; m < 2; m++) {
                    if (base + m * 16 + grp < n) {
                        s[2 * nb] += d[m][0];     s2[2 * nb]     = fmaf(d[m][0], d[m][0], s2[2 * nb]);
                        s[2 * nb + 1] += d[m][1]; s2[2 * nb + 1] = fmaf(d[m][1], d[m][1], s2[2 * nb + 1]);
                    }
                    if (base + m * 16 + grp + 8 < n) {
                        s[2 * nb] += d[m][2];     s2[2 * nb]     = fmaf(d[m][2], d[m][2], s2[2 * nb]);
                        s[2 * nb + 1] += d[m][3]; s2[2 * nb + 1] = fmaf(d[m][3], d[m][3], s2[2 * nb + 1]);
                    }
                }
            }
        }

        float p[2][2] = {{0.f, 0.f}, {0.f, 0.f}};
#pragma unroll
        for (int nb = 0; nb < 4; nb++) {
            float mb0 = s_mb1[nb * 8 + 2 * tg];
            float mb1v = s_mb1[nb * 8 + 2 * tg + 1];
            float d[2][4];
#pragma unroll
            for (int m = 0; m < 2; m++) {
                d[m][0] = mb0; d[m][1] = mb1v; d[m][2] = mb0; d[m][3] = mb1v;
            }
#pragma unroll
            for (int kc = 0; kc < 2; kc++) {
                u32 b0 = smf[(kc * 4 + nb) * 64 + lane];
                u32 b1 = smf[(kc * 4 + nb) * 64 + 32 + lane];
#pragma unroll
                for (int m = 0; m < 2; m++) {
                    MMA16(d[m][0], d[m][1], d[m][2], d[m][3],
                          ah[m][kc][0], ah[m][kc][1], ah[m][kc][2], ah[m][kc][3],
                          b0, b1);
                }
            }
            float mw0 = s_mw2[nb * 8 + 2 * tg];
            float mw1v = s_mw2[nb * 8 + 2 * tg + 1];
#pragma unroll
            for (int m = 0; m < 2; m++) {
                p[m][0] = fmaf(fmaxf(d[m][0], 0.f), mw0,
                          fmaf(fmaxf(d[m][1], 0.f), mw1v, p[m][0]));
                p[m][1] = fmaf(fmaxf(d[m][2], 0.f), mw0,
                          fmaf(fmaxf(d[m][3], 0.f), mw1v, p[m][1]));
            }
        }
#pragma unroll
        for (int m = 0; m < 2; m++) {
            p[m][0] += __shfl_xor_sync(0xffffffffu, p[m][0], 1);
            p[m][0] += __shfl_xor_sync(0xffffffffu, p[m][0], 2);
            p[m][1] += __shfl_xor_sync(0xffffffffu, p[m][1], 1);
            p[m][1] += __shfl_xor_sync(0xffffffffu, p[m][1], 2);
        }
        if (tg == 0) {
#pragma unroll
            for (int m = 0; m < 2; m++) {
                int r = m * 16 + grp;
                if (r < valid)     mask_out[base + r]     = p[m][0] + mb2v;
                if (r + 8 < valid) mask_out[base + r + 8] = p[m][1] + mb2v;
            }
        }
        __syncwarp();
    }

    flush();
#pragma unroll
    for (int i = 0; i < 8; i++) {
#pragma unroll
        for (int o = 4; o < 32; o <<= 1) {
            s[i]  += __shfl_xor_sync(0xffffffffu, s[i],  o);
            s2[i] += __shfl_xor_sync(0xffffffffu, s2[i], o);
        }
    }
    if (grp == 0) {
#pragma unroll
        for (int i = 0; i < 8; i++) {
            int ch = CH(i, tg);
            atomicAdd(&g_sumH[ch],  s[i]);
            atomicAdd(&g_sumH2[ch], s2[i]);
        }
    }
}

// ================= FINALIZE (reads scratch, then re-zeroes it) ===========
__global__ void finalize_kernel(
    const float* __restrict__ w1,
    const float* __restrict__ gamma, const float* __restrict__ beta,
    const float* __restrict__ iou_w, const float* __restrict__ iou_b,
    float* __restrict__ out_pooled, float* __restrict__ out_iou,
    int n, int B)
{
    int t = threadIdx.x;
    float inv = 1.f / (float)n;
    float mu  = g_sumH[t] * inv;
    float var = g_sumH2[t] * inv - mu * mu;
    float sc  = gamma[t] * rsqrtf(var + 1e-4f);
    g_b1f[t] = beta[t] - mu * sc;
#pragma unroll
    for (int k = 0; k < C; k++) g_w1f[k * C + t] = w1[k * C + t] * sc;

    float iw = iou_w[t];
    for (int b = 0; b < B; b++) {
        float cnt = fmaxf(g_cnt[b], 1.f);
        float pm  = g_pool[b * C + t] / cnt;
        out_pooled[b * C + t] = pm;
        float v = pm * iw;
#pragma unroll
        for (int o = 16; o > 0; o >>= 1) v += __shfl_xor_sync(0xffffffffu, v, o);
        if (t == 0) out_iou[b] = v + iou_b[0];
    }

    // restore zeroed-scratch invariant for the next graph replay
    g_sumH[t] = 0.f;
    g_sumH2[t] = 0.f;
    for (int b = 0; b < 64; b++) g_pool[b * C + t] = 0.f;
    if (t < 32) { g_cnt[t] = 0.f; g_cnt[t + 32] = 0.f; }
}

// ================= PASS 2 (R14 math + cp.async double buffer) ============
__global__ void __launch_bounds__(32 * WPB, 4) pass2_kernel(
    const float* __restrict__ feats,
    const float* __restrict__ w2, const float* __restrict__ ob2,
    float* __restrict__ off_out, int n, int tiles_total, int tpw)
{
    __shared__ float sx[WPB][2][TP * XP];

    const int lane = threadIdx.x & 31;
    const int wi   = threadIdx.x >> 5;
    const int tg   = lane & 3;
    const int grp  = lane >> 2;

    u32 Wf[2][4][2];
#pragma unroll
    for (int kc = 0; kc < 2; kc++)
#pragma unroll
        for (int nb = 0; nb < 4; nb++) {
            int col = nb * 8 + grp;
            int k0 = kc * 16 + 2 * tg;
            Wf[kc][nb][0] = packh2(g_w1f[k0 * C + col],       g_w1f[(k0 + 1) * C + col]);
            Wf[kc][nb][1] = packh2(g_w1f[(k0 + 8) * C + col], g_w1f[(k0 + 9) * C + col]);
        }
    float fb[8], w2v0[8], w2v1[8], w2v2[8];
#pragma unroll
    for (int i = 0; i < 8; i++) {
        int ch = CH(i, tg);
        fb[i]   = g_b1f[ch];
        w2v0[i] = w2[ch * 3 + 0];
        w2v1[i] = w2[ch * 3 + 1];
        w2v2[i] = w2[ch * 3 + 2];
    }
    const float c0 = ob2[0], c1 = ob2[1], c2 = ob2[2];

    const int gwid = blockIdx.x * WPB + wi;
    int t0 = gwid * tpw;
    int t1 = t0 + tpw; if (t1 > tiles_total) t1 = tiles_total;
    if (t0 >= t1) return;

    auto issue_tile = [&](int tile, int bsel) {
        int base = tile * TP;
        int valid = n - base; if (valid > TP) valid = TP;
        int lim = valid * 8;
        const float4* src = (const float4*)(feats + (size_t)base * C);
        u32 sa = (u32)__cvta_generic_to_shared(&sx[wi][bsel][0]);
#pragma unroll
        for (int j = 0; j < 8; j++) {
            int L = lane + 32 * j;
            u32 dst = sa + (((L >> 3) * XP + 4 * (L & 7)) << 2);
            int nb = (L < lim) ? 16 : 0;
            const float4* sp = src + ((L < lim) ? L : 0);
            CP_ASYNC16(dst, sp, nb);
        }
        CP_COMMIT();
    };

    issue_tile(t0, 0);

    for (int tile = t0; tile < t1; tile++) {
        const int cur = (tile - t0) & 1;
        const int base = tile * TP;
        int valid = n - base; if (valid > TP) valid = TP;
        const bool has_next = (tile + 1 < t1);

        if (has_next) { issue_tile(tile + 1, cur ^ 1); CP_WAIT1(); }
        else          { CP_WAIT0(); }
        __syncwarp();

        const float* SX = &sx[wi][cur][0];

        u32 ah[2][2][4], al[2][2][4];
#pragma unroll
        for (int m = 0; m < 2; m++)
#pragma unroll
            for (int kc = 0; kc < 2; kc++) {
                int r = m * 16 + grp;
                const float* p0 = &SX[r * XP + kc * 16 + 2 * tg];
                const float* p1 = &SX[(r + 8) * XP + kc * 16 + 2 * tg];
                float2 v0 = *(const float2*)p0;
                float2 v1 = *(const float2*)p1;
                float2 v2 = *(const float2*)(p0 + 8);
                float2 v3 = *(const float2*)(p1 + 8);
                split_h2(v0.x, v0.y, ah[m][kc][0], al[m][kc][0]);
                split_h2(v1.x, v1.y, ah[m][kc][1], al[m][kc][1]);
                split_h2(v2.x, v2.y, ah[m][kc][2], al[m][kc][2]);
                split_h2(v3.x, v3.y, ah[m][kc][3], al[m][kc][3]);
            }

        float o0[2][2], o1[2][2], o2[2][2];
#pragma unroll
        for (int m = 0; m < 2; m++)
#pragma unroll
            for (int r = 0; r < 2; r++) { o0[m][r] = 0.f; o1[m][r] = 0.f; o2[m][r] = 0.f; }

#pragma unroll
        for (int nb = 0; nb < 4; nb++) {
            float d[2][4];
#pragma unroll
            for (int m = 0; m < 2; m++) {
                d[m][0] = fb[2 * nb]; d[m][1] = fb[2 * nb + 1];
                d[m][2] = fb[2 * nb]; d[m][3] = fb[2 * nb + 1];
            }
#pragma unroll
            for (int kc = 0; kc < 2; kc++)
#pragma unroll
                for (int m = 0; m < 2; m++) {
                    MMA16(d[m][0], d[m][1], d[m][2], d[m][3],
                          al[m][kc][0], al[m][kc][1], al[m][kc][2], al[m][kc][3],
                          Wf[kc][nb][0], Wf[kc][nb][1]);
                    MMA16(d[m][0], d[m][1], d[m][2], d[m][3],
                          ah[m][kc][0], ah[m][kc][1], ah[m][kc][2], ah[m][kc][3],
                          Wf[kc][nb][0], Wf[kc][nb][1]);
                }
#pragma unroll
            for (int m = 0; m < 2; m++) {
                float e0 = fmaxf(d[m][0], 0.f), e1 = fmaxf(d[m][1], 0.f);
                float e2 = fmaxf(d[m][2], 0.f), e3 = fmaxf(d[m][3], 0.f);
                o0[m][0] = fmaf(e0, w2v0[2 * nb], fmaf(e1, w2v0[2 * nb + 1], o0[m][0]));
                o1[m][0] = fmaf(e0, w2v1[2 * nb], fmaf(e1, w2v1[2 * nb + 1], o1[m][0]));
                o2[m][0] = fmaf(e0, w2v2[2 * nb], fmaf(e1, w2v2[2 * nb + 1], o2[m][0]));
                o0[m][1] = fmaf(e2, w2v0[2 * nb], fmaf(e3, w2v0[2 * nb + 1], o0[m][1]));
                o1[m][1] = fmaf(e2, w2v1[2 * nb], fmaf(e3, w2v1[2 * nb + 1], o1[m][1]));
                o2[m][1] = fmaf(e2, w2v2[2 * nb], fmaf(e3, w2v2[2 * nb + 1], o2[m][1]));
            }
        }
#pragma unroll
        for (int m = 0; m < 2; m++)
#pragma unroll
            for (int r = 0; r < 2; r++) {
#pragma unroll
                for (int o = 1; o <= 2; o <<= 1) {
                    o0[m][r] += __shfl_xor_sync(0xffffffffu, o0[m][r], o);
                    o1[m][r] += __shfl_xor_sync(0xffffffffu, o1[m][r], o);
                    o2[m][r] += __shfl_xor_sync(0xffffffffu, o2[m][r], o);
                }
            }
        if (tg == 0) {
#pragma unroll
            for (int m = 0; m < 2; m++) {
#pragma unroll
                for (int r = 0; r < 2; r++) {
                    int row = m * 16 + grp + r * 8;
                    if (row < valid) {
                        size_t o = (size_t)(base + row) * 3;
                        off_out[o + 0] = o0[m][r] + c0;
                        off_out[o + 1] = o1[m][r] + c1;
                        off_out[o + 2] = o2[m][r] + c2;
                    }
                }
            }
        }
    }
}

// ================= LAUNCH =================
extern "C" void kernel_launch(void* const* d_in, const int* in_sizes, int n_in,
                              void* d_out, int out_size) {
    const float* feats = (const float*)d_in[0];
    const int*   bidx  = (const int*)  d_in[1];
    const float* w1    = (const float*)d_in[2];
    const float* gamma = (const float*)d_in[4];
    const float* beta  = (const float*)d_in[5];
    const float* w2    = (const float*)d_in[6];
    const float* ob2   = (const float*)d_in[7];
    const float* mw1   = (const float*)d_in[8];
    const float* mb1   = (const float*)d_in[9];
    const float* mw2   = (const float*)d_in[10];
    const float* mb2   = (const float*)d_in[11];
    const float* iw    = (const float*)d_in[12];
    const float* ib    = (const float*)d_in[13];

    int n = in_sizes[1];
    int B = (out_size - 4 * n) / 33;
    if (B < 1) B = 1;
    if (B > 64) B = 64;

    float* out        = (float*)d_out;
    float* out_off    = out;
    float* out_mask   = out + (size_t)3 * n;
    float* out_pooled = out + (size_t)4 * n;
    float* out_iou    = out_pooled + (size_t)B * C;

    int tiles  = (n + TP - 1) / TP;
    int blocks = 608;
    int warps  = blocks * WPB;
    int tpw    = (tiles + warps - 1) / warps;

    pass1_kernel<<<blocks, 32 * WPB>>>(feats, bidx, w1, mw1, mb1, mw2, mb2,
                                       out_mask, n, tiles, tpw);
    finalize_kernel<<<1, 32>>>(w1, gamma, beta, iw, ib,
                               out_pooled, out_iou, n, B);
    pass2_kernel<<<blocks, 32 * WPB>>>(feats, w2, ob2, out_off, n, tiles, tpw);
}